// round 7
// baseline (speedup 1.0000x reference)
#include <cuda_runtime.h>
#include <cuda_bf16.h>
#include <cstdint>

#define SEQ   2048
#define DM    2048
#define NQ    32
#define NKV   8
#define HD    64
#define QKVN  3072
#define BATCH 2
#define MTOT  (BATCH * SEQ)   // 4096
#define NHEAD (BATCH * NQ)    // 64

// 0.125 * log2(e): folded into Q so flash softmax can use raw ex2
#define QSCALE 0.18033688011112042f

// ------------------------- scratch (device globals) -------------------------
__device__ __align__(128) __nv_bfloat16 g_xh[(size_t)MTOT * DM];
__device__ __align__(128) __nv_bfloat16 g_xl[(size_t)MTOT * DM];
__device__ __align__(128) __nv_bfloat16 g_wqth[(size_t)QKVN * DM];
__device__ __align__(128) __nv_bfloat16 g_wqtl[(size_t)QKVN * DM];
__device__ __align__(128) __nv_bfloat16 g_woth[(size_t)DM * DM];
__device__ __align__(128) __nv_bfloat16 g_wotl[(size_t)DM * DM];
__device__ __align__(128) __nv_bfloat16 g_qkvh[(size_t)MTOT * QKVN];
__device__ __align__(128) __nv_bfloat16 g_qkvl[(size_t)MTOT * QKVN];
__device__ __align__(128) __nv_bfloat16 g_ah[(size_t)MTOT * DM];
__device__ __align__(128) __nv_bfloat16 g_al[(size_t)MTOT * DM];

// ------------------------- helpers ------------------------------------------
__device__ __forceinline__ uint32_t smem_u32(const void* p) {
    uint32_t a;
    asm("{ .reg .u64 t; cvta.to.shared.u64 t, %1; cvt.u32.u64 %0, t; }"
        : "=r"(a) : "l"(p));
    return a;
}

#define SMEM_SWIZZLE_128B(o) ((o) ^ (((o) >> 3) & 0x70))

__device__ __forceinline__ void cp16(uint32_t d, const void* s) {
    asm volatile("cp.async.cg.shared.global [%0], [%1], 16;" :: "r"(d), "l"(s));
}
#define CP_COMMIT() asm volatile("cp.async.commit_group;" ::: "memory")

#define LDSM4(R0, R1, R2, R3, A) \
    asm volatile("ldmatrix.sync.aligned.m8n8.x4.shared.b16 {%0,%1,%2,%3}, [%4];" \
                 : "=r"(R0), "=r"(R1), "=r"(R2), "=r"(R3) : "r"(A))
#define LDSM4T(R0, R1, R2, R3, A) \
    asm volatile("ldmatrix.sync.aligned.m8n8.x4.trans.shared.b16 {%0,%1,%2,%3}, [%4];" \
                 : "=r"(R0), "=r"(R1), "=r"(R2), "=r"(R3) : "r"(A))
#define LDSM2(R0, R1, A) \
    asm volatile("ldmatrix.sync.aligned.m8n8.x2.shared.b16 {%0,%1}, [%2];" \
                 : "=r"(R0), "=r"(R1) : "r"(A))

#define MMA16816(C, A, B) \
    asm volatile("mma.sync.aligned.m16n8k16.row.col.f32.bf16.bf16.f32 " \
                 "{%0,%1,%2,%3}, {%4,%5,%6,%7}, {%8,%9}, {%0,%1,%2,%3};" \
                 : "+f"((C)[0]), "+f"((C)[1]), "+f"((C)[2]), "+f"((C)[3]) \
                 : "r"((A)[0]), "r"((A)[1]), "r"((A)[2]), "r"((A)[3]), \
                   "r"((B)[0]), "r"((B)[1]))

union B16x4 { uint2 v; __nv_bfloat16 b[4]; };

__device__ __forceinline__ void split2(float v, __nv_bfloat16& h, __nv_bfloat16& l) {
    h = __float2bfloat16(v);
    l = __float2bfloat16(v - __bfloat162float(h));
}
__device__ __forceinline__ void pk2split(float a, float b, uint32_t& hi, uint32_t& lo) {
    __nv_bfloat162 h, l;
    split2(a, h.x, l.x);
    split2(b, h.y, l.y);
    hi = *(uint32_t*)&h;
    lo = *(uint32_t*)&l;
}
__device__ __forceinline__ float ex2(float x) {
    float y;
    asm("ex2.approx.ftz.f32 %0, %1;" : "=f"(y) : "f"(x));
    return y;
}

// ------------------------- mma.sync GEMM core (3-stage) ----------------------
// BM=128 fixed, 8 warps (2 x 4); warp tile 64 x (BN/4); NT = BN/32 n8-tiles.
template <int BN>
__device__ __forceinline__ void gemm_mma(
    char* smem, int tid,
    const __nv_bfloat16* __restrict__ Ah, const __nv_bfloat16* __restrict__ Al, int lda,
    const __nv_bfloat16* __restrict__ Bh, const __nv_bfloat16* __restrict__ Bl, int ldb,
    int K, float acc[4][BN / 32][4])
{
    constexpr int NT    = BN / 32;
    constexpr int ABY   = 128 * 128;
    constexpr int BBY   = BN * 128;
    constexpr int STAGE = 2 * ABY + 2 * BBY;

    const uint32_t su = smem_u32(smem);
    const int lane = tid & 31, warp = tid >> 5;
    const int wm = warp & 1, wn = warp >> 1;
    const int arow  = wm * 64 + (lane & 15);
    const int acolb = (lane >> 4) * 16;
    const int brow  = wn * (BN / 4) + (lane & 7);
    const int bcolb = ((lane >> 3) & 1) * 16;
    const int nch = K >> 6;

    auto issue = [&](int c) {
        const int k0 = c << 6;
        const uint32_t ub = su + (uint32_t)(c % 3) * STAGE;
        #pragma unroll
        for (int t = 0; t < 4; t++) {
            int i = tid + t * 256;
            int r = i >> 3, q = i & 7;
            uint32_t so = SMEM_SWIZZLE_128B((uint32_t)(r * 128 + q * 16));
            size_t off = (size_t)r * lda + k0 + q * 8;
            cp16(ub + so, Ah + off);
            cp16(ub + ABY + so, Al + off);
        }
        #pragma unroll
        for (int t = 0; t < (BN * 8) / 256; t++) {
            int i = tid + t * 256;
            int r = i >> 3, q = i & 7;
            uint32_t so = SMEM_SWIZZLE_128B((uint32_t)(r * 128 + q * 16));
            size_t off = (size_t)r * ldb + k0 + q * 8;
            cp16(ub + 2 * ABY + so, Bh + off);
            cp16(ub + 2 * ABY + BBY + so, Bl + off);
        }
        CP_COMMIT();
    };

    issue(0);
    if (nch > 1) issue(1);
    for (int c = 0; c < nch; c++) {
        if (c + 1 < nch) {
            asm volatile("cp.async.wait_group 1;" ::: "memory");
        } else {
            asm volatile("cp.async.wait_group 0;" ::: "memory");
        }
        __syncthreads();
        if (c + 2 < nch) issue(c + 2);

        const uint32_t ub = su + (uint32_t)(c % 3) * STAGE;
        #pragma unroll
        for (int ks = 0; ks < 4; ks++) {
            const int kb = ks * 32;
            uint32_t ahr[4][4], alr[4][4], bhr[NT][2], blr[NT][2];
            #pragma unroll
            for (int mt = 0; mt < 4; mt++) {
                uint32_t so = SMEM_SWIZZLE_128B(
                    (uint32_t)((arow + mt * 16) * 128 + kb + acolb));
                LDSM4(ahr[mt][0], ahr[mt][1], ahr[mt][2], ahr[mt][3], ub + so);
                LDSM4(alr[mt][0], alr[mt][1], alr[mt][2], alr[mt][3], ub + ABY + so);
            }
            #pragma unroll
            for (int nt = 0; nt < NT; nt++) {
                uint32_t so = SMEM_SWIZZLE_128B(
                    (uint32_t)((brow + nt * 8) * 128 + kb + bcolb));
                LDSM2(bhr[nt][0], bhr[nt][1], ub + 2 * ABY + so);
                LDSM2(blr[nt][0], blr[nt][1], ub + 2 * ABY + BBY + so);
            }
            #pragma unroll
            for (int mt = 0; mt < 4; mt++)
                #pragma unroll
                for (int nt = 0; nt < NT; nt++) {
                    MMA16816(acc[mt][nt], ahr[mt], bhr[nt]);
                    MMA16816(acc[mt][nt], ahr[mt], blr[nt]);
                    MMA16816(acc[mt][nt], alr[mt], bhr[nt]);
                }
        }
        // no trailing sync: next iteration's top sync orders buffer reuse
    }
}

static constexpr int SMEM_QKV  = 3 * (2 * 128 * 128 + 2 * 96 * 128);   // 172032
static constexpr int SMEM_PROJ = 3 * (2 * 128 * 128 + 2 * 64 * 128);   // 147456
static constexpr int SMEM_FL   = 32768 + 2 * 65536;                    // 163840

// ------------------------- prep kernels -------------------------------------
__global__ __launch_bounds__(256) void k_split(const float* __restrict__ x,
                                               __nv_bfloat16* __restrict__ xh,
                                               __nv_bfloat16* __restrict__ xl) {
    size_t i = ((size_t)blockIdx.x * 256 + threadIdx.x) * 4;
    float4 v = *(const float4*)(x + i);
    B16x4 h, l;
    split2(v.x, h.b[0], l.b[0]); split2(v.y, h.b[1], l.b[1]);
    split2(v.z, h.b[2], l.b[2]); split2(v.w, h.b[3], l.b[3]);
    *(uint2*)(xh + i) = h.v;
    *(uint2*)(xl + i) = l.v;
}

__global__ __launch_bounds__(256) void k_tsplit(const float* __restrict__ W,
                                                __nv_bfloat16* __restrict__ Th,
                                                __nv_bfloat16* __restrict__ Tl,
                                                int K, int N) {
    __shared__ float t[32][33];
    const int n0 = blockIdx.x * 32, k0 = blockIdx.y * 32;
    const int tx = threadIdx.x, ty = threadIdx.y;
    #pragma unroll
    for (int i = 0; i < 4; i++)
        t[ty * 4 + i][tx] = W[(size_t)(k0 + ty * 4 + i) * N + n0 + tx];
    __syncthreads();
    #pragma unroll
    for (int i = 0; i < 4; i++) {
        float v = t[tx][ty * 4 + i];
        __nv_bfloat16 h, l; split2(v, h, l);
        size_t o = (size_t)(n0 + ty * 4 + i) * K + k0 + tx;
        Th[o] = h; Tl[o] = l;
    }
}

// ------------------------- GEMM kernels (qkv, proj) -------------------------
// BN = 96 -> grid (32, 32) = 1024 blocks.
__global__ __launch_bounds__(256, 1) void k_gemm_qkv(
    const __nv_bfloat16* __restrict__ xh, const __nv_bfloat16* __restrict__ xl,
    const __nv_bfloat16* __restrict__ wth, const __nv_bfloat16* __restrict__ wtl,
    const float* __restrict__ bias,
    __nv_bfloat16* __restrict__ qh, __nv_bfloat16* __restrict__ ql) {
    extern __shared__ char smem[];
    const int tid = threadIdx.x;
    const size_t m0 = (size_t)blockIdx.y * 128, n0 = (size_t)blockIdx.x * 96;
    float acc[4][3][4] = {};
    gemm_mma<96>(smem, tid, xh + m0 * DM, xl + m0 * DM, DM,
                 wth + n0 * DM, wtl + n0 * DM, DM, DM, acc);
    const int lane = tid & 31, warp = tid >> 5;
    const int wm = warp & 1, wn = warp >> 1;
    const int g = lane >> 2, tg = lane & 3;
    #pragma unroll
    for (int mt = 0; mt < 4; mt++)
        #pragma unroll
        for (int half = 0; half < 2; half++) {
            const size_t m = m0 + wm * 64 + mt * 16 + g + half * 8;
            #pragma unroll
            for (int nt = 0; nt < 3; nt++) {
                const int nl = wn * 24 + nt * 8 + tg * 2;
                const int col = (int)n0 + nl;
                const float sc0 = (col     < NQ * HD) ? QSCALE : 1.0f;
                const float sc1 = (col + 1 < NQ * HD) ? QSCALE : 1.0f;
                float v0 = (acc[mt][nt][half * 2 + 0] + bias[col])     * sc0;
                float v1 = (acc[mt][nt][half * 2 + 1] + bias[col + 1]) * sc1;
                __nv_bfloat162 hp, lp;
                split2(v0, hp.x, lp.x);
                split2(v1, hp.y, lp.y);
                *(__nv_bfloat162*)(qh + m * QKVN + col) = hp;
                *(__nv_bfloat162*)(ql + m * QKVN + col) = lp;
            }
        }
}

// BN = 64 -> grid (32, 32) = 1024 blocks.
__global__ __launch_bounds__(256, 1) void k_proj(
    const __nv_bfloat16* __restrict__ ah, const __nv_bfloat16* __restrict__ al,
    const __nv_bfloat16* __restrict__ wth, const __nv_bfloat16* __restrict__ wtl,
    const float* __restrict__ bias, float* __restrict__ out) {
    extern __shared__ char smem[];
    const int tid = threadIdx.x;
    const size_t m0 = (size_t)blockIdx.y * 128, n0 = (size_t)blockIdx.x * 64;
    float acc[4][2][4] = {};
    gemm_mma<64>(smem, tid, ah + m0 * DM, al + m0 * DM, DM,
                 wth + n0 * DM, wtl + n0 * DM, DM, DM, acc);
    const int lane = tid & 31, warp = tid >> 5;
    const int wm = warp & 1, wn = warp >> 1;
    const int g = lane >> 2, tg = lane & 3;
    #pragma unroll
    for (int mt = 0; mt < 4; mt++)
        #pragma unroll
        for (int half = 0; half < 2; half++) {
            const size_t m = m0 + wm * 64 + mt * 16 + g + half * 8;
            float* dst = out + m * DM + n0;
            #pragma unroll
            for (int nt = 0; nt < 2; nt++) {
                const int nl = wn * 16 + nt * 8 + tg * 2;
                float2 v;
                v.x = acc[mt][nt][half * 2 + 0] + bias[n0 + nl];
                v.y = acc[mt][nt][half * 2 + 1] + bias[n0 + nl + 1];
                *(float2*)(dst + nl) = v;
            }
        }
}

// ------------------------- fused flash attention ----------------------------
// Grid (SEQ/128, NHEAD). 8 warps, warp w owns Q rows [w*16, w*16+16).
// Q pre-scaled by 0.125*log2e -> base-2 softmax.
// V consumed directly from qkv [seq, d] via ldmatrix.trans (no pre-transpose).
__global__ __launch_bounds__(256, 1) void k_flash(
    const __nv_bfloat16* __restrict__ qkvh, const __nv_bfloat16* __restrict__ qkvl,
    __nv_bfloat16* __restrict__ ah, __nv_bfloat16* __restrict__ al)
{
    extern __shared__ char smem[];
    const uint32_t su = smem_u32(smem);
    const int tid = threadIdx.x, lane = tid & 31, w = tid >> 5;
    const int z = blockIdx.y, b = z >> 5, h = z & 31, kvh = h >> 2;
    const int m0 = blockIdx.x * 128;

    const __nv_bfloat16* Qh = qkvh + ((size_t)(b * SEQ + m0)) * QKVN + h * HD;
    const __nv_bfloat16* Ql = qkvl + ((size_t)(b * SEQ + m0)) * QKVN + h * HD;
    const __nv_bfloat16* Kh = qkvh + (size_t)b * SEQ * QKVN + NQ * HD + kvh * HD;
    const __nv_bfloat16* Kl = qkvl + (size_t)b * SEQ * QKVN + NQ * HD + kvh * HD;
    const __nv_bfloat16* Vh = qkvh + (size_t)b * SEQ * QKVN + (NQ + NKV) * HD + kvh * HD;
    const __nv_bfloat16* Vl = qkvl + (size_t)b * SEQ * QKVN + (NQ + NKV) * HD + kvh * HD;

    #pragma unroll
    for (int t = 0; t < 4; t++) {
        int i = tid + t * 256;
        int r = i >> 3, q = i & 7;
        uint32_t so = SMEM_SWIZZLE_128B((uint32_t)(r * 128 + q * 16));
        size_t off = (size_t)r * QKVN + q * 8;
        cp16(su + so, Qh + off);
        cp16(su + 16384 + so, Ql + off);
    }
    CP_COMMIT();

    // K tile rows = keys (128B = 64 dims x bf16); V identical layout.
    auto issue_kv = [&](int kt) {
        uint32_t ub = su + 32768 + (uint32_t)(kt & 1) * 65536;
        #pragma unroll
        for (int t = 0; t < 4; t++) {
            int i = tid + t * 256;
            int r = i >> 3, q = i & 7;
            uint32_t so = SMEM_SWIZZLE_128B((uint32_t)(r * 128 + q * 16));
            size_t off = (size_t)(kt * 128 + r) * QKVN + q * 8;
            cp16(ub + so, Kh + off);
            cp16(ub + 16384 + so, Kl + off);
            cp16(ub + 32768 + so, Vh + off);
            cp16(ub + 49152 + so, Vl + off);
        }
        CP_COMMIT();
    };

    issue_kv(0);
    asm volatile("cp.async.wait_group 0;" ::: "memory");  // Q + kv0
    __syncthreads();

    uint32_t qhf[4][4], qlf[4][4];
    {
        const int arow = w * 16 + (lane & 15);
        const int acolb = (lane >> 4) * 16;
        #pragma unroll
        for (int ks = 0; ks < 4; ks++) {
            uint32_t so = SMEM_SWIZZLE_128B((uint32_t)(arow * 128 + ks * 32 + acolb));
            LDSM4(qhf[ks][0], qhf[ks][1], qhf[ks][2], qhf[ks][3], su + so);
            LDSM4(qlf[ks][0], qlf[ks][1], qlf[ks][2], qlf[ks][3], su + 16384 + so);
        }
    }

    float accO[8][4] = {};
    float mr0 = -1e30f, mr1 = -1e30f, lr0 = 0.f, lr1 = 0.f;

    const int brow = (lane & 7);
    const int bhi  = ((lane >> 4) & 1) * 8;
    const int bcolb = ((lane >> 3) & 1) * 16;
    // ldmatrix.trans lane addressing for V [k, d] tiles:
    // block index = lane>>3: bit0 -> k half (+8), bit1 -> d half (+8)
    const int vrow_in16 = ((lane >> 3) & 1) * 8 + (lane & 7);
    const int vdhalf    = ((lane >> 4) & 1) * 8;

    for (int kt = 0; kt < 16; kt++) {
        if (kt > 0) {
            asm volatile("cp.async.wait_group 0;" ::: "memory");
            __syncthreads();
        }
        if (kt + 1 < 16) issue_kv(kt + 1);
        const uint32_t ub = su + 32768 + (uint32_t)(kt & 1) * 65536;

        // ---- S = Q K^T (3-term split); Q pre-scaled ----
        float s[16][4] = {};
        #pragma unroll
        for (int np = 0; np < 8; np++) {
            #pragma unroll
            for (int ks = 0; ks < 4; ks++) {
                const int r = np * 16 + brow + bhi;
                uint32_t so = SMEM_SWIZZLE_128B((uint32_t)(r * 128 + ks * 32 + bcolb));
                uint32_t bh[4], bl[4];
                LDSM4(bh[0], bh[1], bh[2], bh[3], ub + so);
                LDSM4(bl[0], bl[1], bl[2], bl[3], ub + 16384 + so);
                MMA16816(s[2 * np],     qhf[ks], bh + 0);
                MMA16816(s[2 * np],     qhf[ks], bl + 0);
                MMA16816(s[2 * np],     qlf[ks], bh + 0);
                MMA16816(s[2 * np + 1], qhf[ks], bh + 2);
                MMA16816(s[2 * np + 1], qhf[ks], bl + 2);
                MMA16816(s[2 * np + 1], qlf[ks], bh + 2);
            }
        }

        // ---- online softmax (base 2) ----
        float mx0 = -1e30f, mx1 = -1e30f;
        #pragma unroll
        for (int nt = 0; nt < 16; nt++) {
            mx0 = fmaxf(mx0, fmaxf(s[nt][0], s[nt][1]));
            mx1 = fmaxf(mx1, fmaxf(s[nt][2], s[nt][3]));
        }
        #pragma unroll
        for (int o = 1; o <= 2; o <<= 1) {
            mx0 = fmaxf(mx0, __shfl_xor_sync(0xffffffffu, mx0, o));
            mx1 = fmaxf(mx1, __shfl_xor_sync(0xffffffffu, mx1, o));
        }
        const float mn0 = fmaxf(mr0, mx0), mn1 = fmaxf(mr1, mx1);
        const float a0 = ex2(mr0 - mn0), a1 = ex2(mr1 - mn1);
        mr0 = mn0; mr1 = mn1;
        float ls0 = 0.f, ls1 = 0.f;
        #pragma unroll
        for (int nt = 0; nt < 16; nt++) {
            s[nt][0] = ex2(s[nt][0] - mn0);
            s[nt][1] = ex2(s[nt][1] - mn0);
            s[nt][2] = ex2(s[nt][2] - mn1);
            s[nt][3] = ex2(s[nt][3] - mn1);
            ls0 += s[nt][0] + s[nt][1];
            ls1 += s[nt][2] + s[nt][3];
        }
        #pragma unroll
        for (int o = 1; o <= 2; o <<= 1) {
            ls0 += __shfl_xor_sync(0xffffffffu, ls0, o);
            ls1 += __shfl_xor_sync(0xffffffffu, ls1, o);
        }
        lr0 = lr0 * a0 + ls0;
        lr1 = lr1 * a1 + ls1;
        #pragma unroll
        for (int nt2 = 0; nt2 < 8; nt2++) {
            accO[nt2][0] *= a0; accO[nt2][1] *= a0;
            accO[nt2][2] *= a1; accO[nt2][3] *= a1;
        }

        // ---- O += P V (P hi/lo; V hi+lo; 3-term); V via ldmatrix.trans ----
        #pragma unroll
        for (int kp = 0; kp < 8; kp++) {
            uint32_t pfh[4], pfl[4];
            pk2split(s[2 * kp][0],     s[2 * kp][1],     pfh[0], pfl[0]);
            pk2split(s[2 * kp][2],     s[2 * kp][3],     pfh[1], pfl[1]);
            pk2split(s[2 * kp + 1][0], s[2 * kp + 1][1], pfh[2], pfl[2]);
            pk2split(s[2 * kp + 1][2], s[2 * kp + 1][3], pfh[3], pfl[3]);
            const int krow = kp * 16 + vrow_in16;
            #pragma unroll
            for (int ntp = 0; ntp < 4; ntp++) {
                const int d = ntp * 16 + vdhalf;
                uint32_t so = SMEM_SWIZZLE_128B((uint32_t)(krow * 128 + d * 2));
                uint32_t vh[4], vl[4];
                LDSM4T(vh[0], vh[1], vh[2], vh[3], ub + 32768 + so);
                LDSM4T(vl[0], vl[1], vl[2], vl[3], ub + 49152 + so);
                MMA16816(accO[2 * ntp],     pfh, vh + 0);
                MMA16816(accO[2 * ntp],     pfh, vl + 0);
                MMA16816(accO[2 * ntp],     pfl, vh + 0);
                MMA16816(accO[2 * ntp + 1], pfh, vh + 2);
                MMA16816(accO[2 * ntp + 1], pfh, vl + 2);
                MMA16816(accO[2 * ntp + 1], pfl, vh + 2);
            }
        }
    }

    const float i0 = 1.0f / lr0, i1 = 1.0f / lr1;
    const int g = lane >> 2, tg = lane & 3;
    const size_t r0 = (size_t)b * SEQ + m0 + w * 16 + g;
    const size_t r1 = r0 + 8;
    #pragma unroll
    for (int nt2 = 0; nt2 < 8; nt2++) {
        const int d = nt2 * 8 + tg * 2;
        __nv_bfloat162 hp, lp;
        split2(accO[nt2][0] * i0, hp.x, lp.x);
        split2(accO[nt2][1] * i0, hp.y, lp.y);
        *(__nv_bfloat162*)(ah + r0 * DM + h * HD + d) = hp;
        *(__nv_bfloat162*)(al + r0 * DM + h * HD + d) = lp;
        split2(accO[nt2][2] * i1, hp.x, lp.x);
        split2(accO[nt2][3] * i1, hp.y, lp.y);
        *(__nv_bfloat162*)(ah + r1 * DM + h * HD + d) = hp;
        *(__nv_bfloat162*)(al + r1 * DM + h * HD + d) = lp;
    }
}

// ------------------------- host ---------------------------------------------
extern "C" void kernel_launch(void* const* d_in, const int* in_sizes, int n_in,
                              void* d_out, int out_size) {
    const float* x    = (const float*)d_in[0];
    const float* Wqkv = (const float*)d_in[1];
    const float* bqkv = (const float*)d_in[2];
    const float* Wo   = (const float*)d_in[3];
    const float* bo   = (const float*)d_in[4];
    float* out = (float*)d_out;

    __nv_bfloat16 *xh, *xl, *wqth, *wqtl, *woth, *wotl, *qkvh, *qkvl, *ah, *al;
    cudaGetSymbolAddress((void**)&xh, g_xh);     cudaGetSymbolAddress((void**)&xl, g_xl);
    cudaGetSymbolAddress((void**)&wqth, g_wqth); cudaGetSymbolAddress((void**)&wqtl, g_wqtl);
    cudaGetSymbolAddress((void**)&woth, g_woth); cudaGetSymbolAddress((void**)&wotl, g_wotl);
    cudaGetSymbolAddress((void**)&qkvh, g_qkvh); cudaGetSymbolAddress((void**)&qkvl, g_qkvl);
    cudaGetSymbolAddress((void**)&ah, g_ah);     cudaGetSymbolAddress((void**)&al, g_al);

    cudaFuncSetAttribute(k_gemm_qkv, cudaFuncAttributeMaxDynamicSharedMemorySize, SMEM_QKV);
    cudaFuncSetAttribute(k_flash,    cudaFuncAttributeMaxDynamicSharedMemorySize, SMEM_FL);
    cudaFuncSetAttribute(k_proj,     cudaFuncAttributeMaxDynamicSharedMemorySize, SMEM_PROJ);

    k_split<<<(size_t)MTOT * DM / 1024, 256>>>(x, xh, xl);
    k_tsplit<<<dim3(QKVN / 32, DM / 32), dim3(32, 8)>>>(Wqkv, wqth, wqtl, DM, QKVN);
    k_tsplit<<<dim3(DM / 32, DM / 32), dim3(32, 8)>>>(Wo, woth, wotl, DM, DM);

    k_gemm_qkv<<<dim3(QKVN / 96, MTOT / 128), 256, SMEM_QKV>>>(
        xh, xl, wqth, wqtl, bqkv, qkvh, qkvl);

    k_flash<<<dim3(SEQ / 128, NHEAD), 256, SMEM_FL>>>(qkvh, qkvl, ah, al);

    k_proj<<<dim3(DM / 64, MTOT / 128), 256, SMEM_PROJ>>>(ah, al, woth, wotl, bo, out);
}